// round 1
// baseline (speedup 1.0000x reference)
#include <cuda_runtime.h>

// AxialAttention: x[8,128,128,128] fp32, two axial MHA passes (along H, along W),
// HEADS=8, head_dim=16, out = pass0 + pass1.
//
// One CTA per (pass, sequence). 256 threads as a 16x16 grid (tx = lane group of 16).
// Smem: X tile, P buffer, per-head Q/V/O, K^T, and transposed per-head weight slices.

#define TOK 128      // tokens per sequence
#define DIM 128      // embedding dim
#define NHEADS 8
#define EHEAD 16

// smem float counts
#define XS_STRIDE 132
#define QV_STRIDE 17
#define KT_STRIDE 132

template <int PASS>
__launch_bounds__(256)
__global__ void axial_attn_kernel(const float* __restrict__ x,
                                  const float* __restrict__ Wq,
                                  const float* __restrict__ Wkv,
                                  const float* __restrict__ Wo,
                                  const float* __restrict__ bo,
                                  float* __restrict__ out)
{
    extern __shared__ float sm[];
    float* Xs  = sm;                          // [128][132]
    float* Ps  = Xs  + 128 * XS_STRIDE;       // [128][132]
    float* Qh  = Ps  + 128 * XS_STRIDE;       // [128][17]
    float* Vh  = Qh  + 128 * QV_STRIDE;       // [128][17]
    float* Oh  = Vh  + 128 * QV_STRIDE;       // [128][17]
    float* KhT = Oh  + 128 * QV_STRIDE;       // [16][132]  (K transposed: [e][j])
    float* WqT = KhT + 16 * KT_STRIDE;        // [16][132]  (weight slices transposed: [c][d])
    float* WkT = WqT + 16 * KT_STRIDE;
    float* WvT = WkT + 16 * KT_STRIDE;

    const int tid = threadIdx.x;
    const int tx  = tid & 15;    // lanes 0..15 within each half-warp
    const int ty  = tid >> 4;
    const int s   = blockIdx.x;

    long base;
    int  tstride;
    if (PASS == 0) {
        // sequence = (b, w), token = h:  addr = b*128^3 + t*128^2 + w*128 + d
        base = (long)(s >> 7) * 2097152 + (long)(s & 127) * 128;
        tstride = 16384;
    } else {
        // sequence = (b, h), token = w:  addr = (b*128+h)*128^2 + t*128 + d
        base = (long)s * 16384;
        tstride = 128;
    }

    // ---- load X tile [128 tokens][128 dims] into smem (float4, coalesced) ----
    for (int i = tid; i < 128 * 32; i += 256) {
        int t = i >> 5;
        int c = (i & 31) << 2;
        float4 v = *reinterpret_cast<const float4*>(x + base + (long)t * tstride + c);
        *reinterpret_cast<float4*>(&Xs[t * XS_STRIDE + c]) = v;
    }
    __syncthreads();

    // persistent output accumulators: rows ty*8..+8, cols tx*8..+8
    float acc[8][8];
#pragma unroll
    for (int i = 0; i < 8; ++i)
#pragma unroll
        for (int j = 0; j < 8; ++j) acc[i][j] = 0.0f;

    for (int h = 0; h < NHEADS; ++h) {
        // ---- stage per-head weight slices, transposed to [c][d] for vector loads ----
        for (int i = tid; i < 128 * EHEAD; i += 256) {
            int d = i >> 4;
            int c = i & 15;
            WqT[c * KT_STRIDE + d] = Wq [d * 128 + h * 16 + c];
            WkT[c * KT_STRIDE + d] = Wkv[d * 256 + h * 16 + c];
            WvT[c * KT_STRIDE + d] = Wkv[d * 256 + 128 + h * 16 + c];
        }
        __syncthreads();

        // ---- A: per-head projections Q,K,V  (rows ty*8..+8, col e=tx) ----
        {
            float qa[8], ka[8], va[8];
#pragma unroll
            for (int r = 0; r < 8; ++r) { qa[r] = 0.f; ka[r] = 0.f; va[r] = 0.f; }

            for (int d0 = 0; d0 < 128; d0 += 4) {
                float4 wq = *reinterpret_cast<const float4*>(&WqT[tx * KT_STRIDE + d0]);
                float4 wk = *reinterpret_cast<const float4*>(&WkT[tx * KT_STRIDE + d0]);
                float4 wv = *reinterpret_cast<const float4*>(&WvT[tx * KT_STRIDE + d0]);
#pragma unroll
                for (int r = 0; r < 8; ++r) {
                    float4 xv = *reinterpret_cast<const float4*>(&Xs[(ty * 8 + r) * XS_STRIDE + d0]);
                    qa[r] += xv.x * wq.x; qa[r] += xv.y * wq.y;
                    qa[r] += xv.z * wq.z; qa[r] += xv.w * wq.w;
                    ka[r] += xv.x * wk.x; ka[r] += xv.y * wk.y;
                    ka[r] += xv.z * wk.z; ka[r] += xv.w * wk.w;
                    va[r] += xv.x * wv.x; va[r] += xv.y * wv.y;
                    va[r] += xv.z * wv.z; va[r] += xv.w * wv.w;
                }
            }
#pragma unroll
            for (int r = 0; r < 8; ++r) {
                int row = ty * 8 + r;
                Qh[row * QV_STRIDE + tx] = qa[r];
                Vh[row * QV_STRIDE + tx] = va[r];
                KhT[tx * KT_STRIDE + row] = ka[r];   // transposed store
            }
        }
        __syncthreads();

        // ---- B: S = (Q K^T) * 0.25, softmax over cols -> Ps ----
        {
            float sreg[8][8];
#pragma unroll
            for (int i = 0; i < 8; ++i)
#pragma unroll
                for (int j = 0; j < 8; ++j) sreg[i][j] = 0.0f;

            for (int e = 0; e < EHEAD; ++e) {
                float qv[8], kv[8];
#pragma unroll
                for (int r = 0; r < 8; ++r) qv[r] = Qh[(ty * 8 + r) * QV_STRIDE + e];
#pragma unroll
                for (int r = 0; r < 8; ++r) kv[r] = KhT[e * KT_STRIDE + tx * 8 + r];
#pragma unroll
                for (int ri = 0; ri < 8; ++ri)
#pragma unroll
                    for (int rj = 0; rj < 8; ++rj) sreg[ri][rj] += qv[ri] * kv[rj];
            }

            float mrow[8], srow[8];
#pragma unroll
            for (int ri = 0; ri < 8; ++ri) {
                float m = -1e30f;
#pragma unroll
                for (int rj = 0; rj < 8; ++rj) {
                    sreg[ri][rj] *= 0.25f;
                    m = fmaxf(m, sreg[ri][rj]);
                }
                mrow[ri] = m;
            }
#pragma unroll
            for (int ri = 0; ri < 8; ++ri) {
                mrow[ri] = fmaxf(mrow[ri], __shfl_xor_sync(0xffffffffu, mrow[ri], 1));
                mrow[ri] = fmaxf(mrow[ri], __shfl_xor_sync(0xffffffffu, mrow[ri], 2));
                mrow[ri] = fmaxf(mrow[ri], __shfl_xor_sync(0xffffffffu, mrow[ri], 4));
                mrow[ri] = fmaxf(mrow[ri], __shfl_xor_sync(0xffffffffu, mrow[ri], 8));
            }
#pragma unroll
            for (int ri = 0; ri < 8; ++ri) {
                float ssum = 0.0f;
#pragma unroll
                for (int rj = 0; rj < 8; ++rj) {
                    float ev = __expf(sreg[ri][rj] - mrow[ri]);
                    sreg[ri][rj] = ev;
                    ssum += ev;
                }
                srow[ri] = ssum;
            }
#pragma unroll
            for (int ri = 0; ri < 8; ++ri) {
                srow[ri] += __shfl_xor_sync(0xffffffffu, srow[ri], 1);
                srow[ri] += __shfl_xor_sync(0xffffffffu, srow[ri], 2);
                srow[ri] += __shfl_xor_sync(0xffffffffu, srow[ri], 4);
                srow[ri] += __shfl_xor_sync(0xffffffffu, srow[ri], 8);
            }
#pragma unroll
            for (int ri = 0; ri < 8; ++ri) {
                float inv = 1.0f / srow[ri];
                float4 a, b;
                a.x = sreg[ri][0] * inv; a.y = sreg[ri][1] * inv;
                a.z = sreg[ri][2] * inv; a.w = sreg[ri][3] * inv;
                b.x = sreg[ri][4] * inv; b.y = sreg[ri][5] * inv;
                b.z = sreg[ri][6] * inv; b.w = sreg[ri][7] * inv;
                float* dst = &Ps[(ty * 8 + ri) * XS_STRIDE + tx * 8];
                *reinterpret_cast<float4*>(dst)     = a;
                *reinterpret_cast<float4*>(dst + 4) = b;
            }
        }
        __syncthreads();

        // ---- C: O = P @ V_head  (rows ty*8..+8, col e=tx) ----
        {
            float oa[8];
#pragma unroll
            for (int r = 0; r < 8; ++r) oa[r] = 0.0f;

            for (int j = 0; j < 128; j += 4) {
                float v0 = Vh[(j + 0) * QV_STRIDE + tx];
                float v1 = Vh[(j + 1) * QV_STRIDE + tx];
                float v2 = Vh[(j + 2) * QV_STRIDE + tx];
                float v3 = Vh[(j + 3) * QV_STRIDE + tx];
#pragma unroll
                for (int r = 0; r < 8; ++r) {
                    float4 p = *reinterpret_cast<const float4*>(&Ps[(ty * 8 + r) * XS_STRIDE + j]);
                    oa[r] += p.x * v0; oa[r] += p.y * v1;
                    oa[r] += p.z * v2; oa[r] += p.w * v3;
                }
            }
#pragma unroll
            for (int r = 0; r < 8; ++r) Oh[(ty * 8 + r) * QV_STRIDE + tx] = oa[r];
        }
        __syncthreads();

        // ---- D: acc += O_head @ Wo[h*16 : h*16+16, :] ----
        {
#pragma unroll
            for (int e = 0; e < EHEAD; ++e) {
                const float* wrow = &Wo[(h * 16 + e) * 128 + tx * 8];
                float4 w0 = *reinterpret_cast<const float4*>(wrow);
                float4 w1 = *reinterpret_cast<const float4*>(wrow + 4);
#pragma unroll
                for (int r = 0; r < 8; ++r) {
                    float ov = Oh[(ty * 8 + r) * QV_STRIDE + e];
                    acc[r][0] += ov * w0.x; acc[r][1] += ov * w0.y;
                    acc[r][2] += ov * w0.z; acc[r][3] += ov * w0.w;
                    acc[r][4] += ov * w1.x; acc[r][5] += ov * w1.y;
                    acc[r][6] += ov * w1.z; acc[r][7] += ov * w1.w;
                }
            }
        }
        // no barrier needed here: next-head staging writes WqT/WkT/WvT (not read by D),
        // and the staging barrier orders all of D before next A's Qh/Kh/Vh writes.
    }

    // ---- epilogue: + bias, write (pass 0) or read-modify-write (pass 1) ----
    float4 b0 = *reinterpret_cast<const float4*>(&bo[tx * 8]);
    float4 b1 = *reinterpret_cast<const float4*>(&bo[tx * 8 + 4]);
#pragma unroll
    for (int r = 0; r < 8; ++r) {
        long o = base + (long)(ty * 8 + r) * tstride + tx * 8;
        float4 v0, v1;
        v0.x = acc[r][0] + b0.x; v0.y = acc[r][1] + b0.y;
        v0.z = acc[r][2] + b0.z; v0.w = acc[r][3] + b0.w;
        v1.x = acc[r][4] + b1.x; v1.y = acc[r][5] + b1.y;
        v1.z = acc[r][6] + b1.z; v1.w = acc[r][7] + b1.w;
        if (PASS == 0) {
            *reinterpret_cast<float4*>(&out[o])     = v0;
            *reinterpret_cast<float4*>(&out[o + 4]) = v1;
        } else {
            float4 p0 = *reinterpret_cast<const float4*>(&out[o]);
            float4 p1 = *reinterpret_cast<const float4*>(&out[o + 4]);
            v0.x += p0.x; v0.y += p0.y; v0.z += p0.z; v0.w += p0.w;
            v1.x += p1.x; v1.y += p1.y; v1.z += p1.z; v1.w += p1.w;
            *reinterpret_cast<float4*>(&out[o])     = v0;
            *reinterpret_cast<float4*>(&out[o + 4]) = v1;
        }
    }
}

extern "C" void kernel_launch(void* const* d_in, const int* in_sizes, int n_in,
                              void* d_out, int out_size)
{
    const float* x    = (const float*)d_in[0];
    const float* Wq0  = (const float*)d_in[1];
    const float* Wkv0 = (const float*)d_in[2];
    const float* Wo0  = (const float*)d_in[3];
    const float* bo0  = (const float*)d_in[4];
    const float* Wq1  = (const float*)d_in[5];
    const float* Wkv1 = (const float*)d_in[6];
    const float* Wo1  = (const float*)d_in[7];
    const float* bo1  = (const float*)d_in[8];
    float* out = (float*)d_out;

    const int smem_floats = 2 * 128 * XS_STRIDE   // Xs, Ps
                          + 3 * 128 * QV_STRIDE   // Qh, Vh, Oh
                          + 4 * 16 * KT_STRIDE;   // KhT, WqT, WkT, WvT
    const int smem_bytes = smem_floats * 4;       // 195,072 B

    cudaFuncSetAttribute(axial_attn_kernel<0>,
                         cudaFuncAttributeMaxDynamicSharedMemorySize, smem_bytes);
    cudaFuncSetAttribute(axial_attn_kernel<1>,
                         cudaFuncAttributeMaxDynamicSharedMemorySize, smem_bytes);

    // pass 0 (attend along H) writes out; pass 1 (attend along W) accumulates.
    axial_attn_kernel<0><<<1024, 256, smem_bytes>>>(x, Wq0, Wkv0, Wo0, bo0, out);
    axial_attn_kernel<1><<<1024, 256, smem_bytes>>>(x, Wq1, Wkv1, Wo1, bo1, out);
}

// round 2
// speedup vs baseline: 1.0945x; 1.0945x over previous
#include <cuda_runtime.h>

// AxialAttention via packed f32x2 FMAs (sm_103a FFMA2).
// x[8,128,128,128] fp32, two axial MHA passes (along H, along W), HEADS=8, e=16.
// One CTA per (pass, sequence); 256 threads as 16x16 (tx = half-warp lane).

#define NHEADS 8
#define EHEAD 16

#define XT_STRIDE 132   // Xt[d][t]
#define PS_STRIDE 132   // Ps[i][j]
#define QO_STRIDE 17    // Qh/Oh [t][e]
#define KT_STRIDE 132   // KhT/VhT/W*T [e|c][t|d]

typedef unsigned long long ull;

__device__ __forceinline__ void ffma2(ull& d, ull a, ull b) {
    asm("fma.rn.f32x2 %0, %1, %2, %0;" : "+l"(d) : "l"(a), "l"(b));
}
__device__ __forceinline__ ull fadd2(ull a, ull b) {
    ull r; asm("add.rn.f32x2 %0, %1, %2;" : "=l"(r) : "l"(a), "l"(b)); return r;
}
__device__ __forceinline__ ull pack2(float lo, float hi) {
    ull r; asm("mov.b64 %0, {%1, %2};" : "=l"(r) : "f"(lo), "f"(hi)); return r;
}
__device__ __forceinline__ float2 unpack2(ull v) {
    float2 r; asm("mov.b64 {%0, %1}, %2;" : "=f"(r.x), "=f"(r.y) : "l"(v)); return r;
}

template <int PASS>
__launch_bounds__(256)
__global__ void axial_attn_kernel(const float* __restrict__ x,
                                  const float* __restrict__ Wq,
                                  const float* __restrict__ Wkv,
                                  const float* __restrict__ Wo,
                                  const float* __restrict__ bo,
                                  float* __restrict__ out)
{
    extern __shared__ float sm[];
    float* Xt  = sm;                          // [128 d][132]  (X transposed: [d][t])
    float* Ps  = Xt  + 128 * XT_STRIDE;       // [128 i][132]
    float* Qh  = Ps  + 128 * PS_STRIDE;       // [128 t][17]
    float* Oh  = Qh  + 128 * QO_STRIDE;       // [128 t][17]
    float* KhT = Oh  + 128 * QO_STRIDE;       // [16 e][132]   (K^T: [e][j])
    float* VhT = KhT + 16 * KT_STRIDE;        // [16 e][132]   (V^T: [e][j])
    float* WqT = VhT + 16 * KT_STRIDE;        // [16 c][132]   (weights: [c][d])
    float* WkT = WqT + 16 * KT_STRIDE;
    float* WvT = WkT + 16 * KT_STRIDE;

    const int tid = threadIdx.x;
    const int tx  = tid & 15;
    const int ty  = tid >> 4;
    const int s   = blockIdx.x;
    const int r0  = ty * 8;

    long base;
    int  tstride;
    if (PASS == 0) {
        base = (long)(s >> 7) * 2097152 + (long)(s & 127) * 128;
        tstride = 16384;
    } else {
        base = (long)s * 16384;
        tstride = 128;
    }

    // ---- load X and transpose into Xt[d][t] (coalesced gmem, 4-way STS conflicts ok) ----
    for (int i = tid; i < 128 * 64; i += 256) {
        int t = i >> 6;
        int d = (i & 63) << 1;
        float2 v = *reinterpret_cast<const float2*>(x + base + (long)t * tstride + d);
        Xt[d * XT_STRIDE + t]       = v.x;
        Xt[(d + 1) * XT_STRIDE + t] = v.y;
    }
    __syncthreads();

    // persistent packed out-proj accumulators: rows r0..r0+8, col pairs tx*8+2c
    ull accD[8][4];
#pragma unroll
    for (int i = 0; i < 8; ++i)
#pragma unroll
        for (int c = 0; c < 4; ++c) accD[i][c] = 0ull;

    for (int h = 0; h < NHEADS; ++h) {
        // ---- stage per-head weight slices W*T[c][d] ----
        for (int i = tid; i < 128 * EHEAD; i += 256) {
            int d = i >> 4;
            int c = i & 15;
            WqT[c * KT_STRIDE + d] = Wq [d * 128 + h * 16 + c];
            WkT[c * KT_STRIDE + d] = Wkv[d * 256 + h * 16 + c];
            WvT[c * KT_STRIDE + d] = Wkv[d * 256 + 128 + h * 16 + c];
        }
        __syncthreads();

        // ---- A: Q,K,V projections, packed over row(t)-pairs. col e = tx ----
        {
            ull qa[4], ka[4], va[4];
#pragma unroll
            for (int p = 0; p < 4; ++p) { qa[p] = 0ull; ka[p] = 0ull; va[p] = 0ull; }

            const float* wq = &WqT[tx * KT_STRIDE];
            const float* wk = &WkT[tx * KT_STRIDE];
            const float* wv = &WvT[tx * KT_STRIDE];

#pragma unroll 4
            for (int d0 = 0; d0 < 128; d0 += 4) {
                float4 w4q = *reinterpret_cast<const float4*>(wq + d0);
                float4 w4k = *reinterpret_cast<const float4*>(wk + d0);
                float4 w4v = *reinterpret_cast<const float4*>(wv + d0);
                const float wqv[4] = {w4q.x, w4q.y, w4q.z, w4q.w};
                const float wkv[4] = {w4k.x, w4k.y, w4k.z, w4k.w};
                const float wvv[4] = {w4v.x, w4v.y, w4v.z, w4v.w};
#pragma unroll
                for (int dd = 0; dd < 4; ++dd) {
                    const float* xr = &Xt[(d0 + dd) * XT_STRIDE + r0];
                    ulonglong2 xp01 = *reinterpret_cast<const ulonglong2*>(xr);
                    ulonglong2 xp23 = *reinterpret_cast<const ulonglong2*>(xr + 4);
                    ull wq2 = pack2(wqv[dd], wqv[dd]);
                    ull wk2 = pack2(wkv[dd], wkv[dd]);
                    ull wv2 = pack2(wvv[dd], wvv[dd]);
                    ffma2(qa[0], xp01.x, wq2); ffma2(qa[1], xp01.y, wq2);
                    ffma2(qa[2], xp23.x, wq2); ffma2(qa[3], xp23.y, wq2);
                    ffma2(ka[0], xp01.x, wk2); ffma2(ka[1], xp01.y, wk2);
                    ffma2(ka[2], xp23.x, wk2); ffma2(ka[3], xp23.y, wk2);
                    ffma2(va[0], xp01.x, wv2); ffma2(va[1], xp01.y, wv2);
                    ffma2(va[2], xp23.x, wv2); ffma2(va[3], xp23.y, wv2);
                }
            }
#pragma unroll
            for (int p = 0; p < 4; ++p) {
                int row = r0 + 2 * p;
                float2 q = unpack2(qa[p]);
                Qh[row * QO_STRIDE + tx]       = q.x;
                Qh[(row + 1) * QO_STRIDE + tx] = q.y;
                *reinterpret_cast<float2*>(&KhT[tx * KT_STRIDE + row]) = unpack2(ka[p]);
                *reinterpret_cast<float2*>(&VhT[tx * KT_STRIDE + row]) = unpack2(va[p]);
            }
        }
        __syncthreads();

        // ---- B: S = (Q K^T)*0.25, packed over j-pairs; softmax over j -> Ps ----
        {
            ull s2[8][4];
#pragma unroll
            for (int r = 0; r < 8; ++r)
#pragma unroll
                for (int c = 0; c < 4; ++c) s2[r][c] = 0ull;

#pragma unroll 4
            for (int e = 0; e < EHEAD; ++e) {
                const float* kr = &KhT[e * KT_STRIDE + tx * 8];
                ulonglong2 k01 = *reinterpret_cast<const ulonglong2*>(kr);
                ulonglong2 k23 = *reinterpret_cast<const ulonglong2*>(kr + 4);
#pragma unroll
                for (int r = 0; r < 8; ++r) {
                    float q = Qh[(r0 + r) * QO_STRIDE + e];
                    ull q2 = pack2(q, q);
                    ffma2(s2[r][0], q2, k01.x); ffma2(s2[r][1], q2, k01.y);
                    ffma2(s2[r][2], q2, k23.x); ffma2(s2[r][3], q2, k23.y);
                }
            }

            // unpack, scale, softmax (row reductions across tx via half-warp shfl)
            float sreg[8][8];
#pragma unroll
            for (int r = 0; r < 8; ++r)
#pragma unroll
                for (int c = 0; c < 4; ++c) {
                    float2 v = unpack2(s2[r][c]);
                    sreg[r][2 * c]     = v.x * 0.25f;
                    sreg[r][2 * c + 1] = v.y * 0.25f;
                }

            float mrow[8], srow[8];
#pragma unroll
            for (int r = 0; r < 8; ++r) {
                float m = sreg[r][0];
#pragma unroll
                for (int j = 1; j < 8; ++j) m = fmaxf(m, sreg[r][j]);
                m = fmaxf(m, __shfl_xor_sync(0xffffffffu, m, 1));
                m = fmaxf(m, __shfl_xor_sync(0xffffffffu, m, 2));
                m = fmaxf(m, __shfl_xor_sync(0xffffffffu, m, 4));
                m = fmaxf(m, __shfl_xor_sync(0xffffffffu, m, 8));
                mrow[r] = m;
            }
#pragma unroll
            for (int r = 0; r < 8; ++r) {
                float ssum = 0.0f;
#pragma unroll
                for (int j = 0; j < 8; ++j) {
                    float ev = __expf(sreg[r][j] - mrow[r]);
                    sreg[r][j] = ev;
                    ssum += ev;
                }
                ssum += __shfl_xor_sync(0xffffffffu, ssum, 1);
                ssum += __shfl_xor_sync(0xffffffffu, ssum, 2);
                ssum += __shfl_xor_sync(0xffffffffu, ssum, 4);
                ssum += __shfl_xor_sync(0xffffffffu, ssum, 8);
                srow[r] = ssum;
            }
#pragma unroll
            for (int r = 0; r < 8; ++r) {
                float inv = 1.0f / srow[r];
                float4 a, b;
                a.x = sreg[r][0] * inv; a.y = sreg[r][1] * inv;
                a.z = sreg[r][2] * inv; a.w = sreg[r][3] * inv;
                b.x = sreg[r][4] * inv; b.y = sreg[r][5] * inv;
                b.z = sreg[r][6] * inv; b.w = sreg[r][7] * inv;
                float* dst = &Ps[(r0 + r) * PS_STRIDE + tx * 8];
                *reinterpret_cast<float4*>(dst)     = a;
                *reinterpret_cast<float4*>(dst + 4) = b;
            }
        }
        __syncthreads();

        // ---- C: O = P @ V, packed over reduction dim j (pair x pair, no packs) ----
        {
            ull o2[8];
#pragma unroll
            for (int r = 0; r < 8; ++r) o2[r] = 0ull;

            const float* vt = &VhT[tx * KT_STRIDE];
#pragma unroll 4
            for (int j = 0; j < 128; j += 4) {
                ulonglong2 vv = *reinterpret_cast<const ulonglong2*>(vt + j);
#pragma unroll
                for (int r = 0; r < 8; ++r) {
                    ulonglong2 pp = *reinterpret_cast<const ulonglong2*>(&Ps[(r0 + r) * PS_STRIDE + j]);
                    ffma2(o2[r], pp.x, vv.x);
                    ffma2(o2[r], pp.y, vv.y);
                }
            }
#pragma unroll
            for (int r = 0; r < 8; ++r) {
                float2 v = unpack2(o2[r]);
                Oh[(r0 + r) * QO_STRIDE + tx] = v.x + v.y;
            }
        }
        __syncthreads();

        // ---- D: accD += O_head @ Wo[h*16+e, :], packed over output col-pairs ----
        {
#pragma unroll 4
            for (int e = 0; e < EHEAD; ++e) {
                const float* wrow = &Wo[(h * 16 + e) * 128 + tx * 8];
                ulonglong2 w01 = *reinterpret_cast<const ulonglong2*>(wrow);
                ulonglong2 w23 = *reinterpret_cast<const ulonglong2*>(wrow + 4);
#pragma unroll
                for (int r = 0; r < 8; ++r) {
                    float o = Oh[(r0 + r) * QO_STRIDE + e];
                    ull o2 = pack2(o, o);
                    ffma2(accD[r][0], o2, w01.x);
                    ffma2(accD[r][1], o2, w01.y);
                    ffma2(accD[r][2], o2, w23.x);
                    ffma2(accD[r][3], o2, w23.y);
                }
            }
        }
        // staging barrier at next loop head orders D's Oh reads vs next A's writes
    }

    // ---- epilogue: + bias; write (pass 0) or packed RMW (pass 1) ----
    ulonglong2 bA = *reinterpret_cast<const ulonglong2*>(&bo[tx * 8]);
    ulonglong2 bB = *reinterpret_cast<const ulonglong2*>(&bo[tx * 8 + 4]);
#pragma unroll
    for (int r = 0; r < 8; ++r) {
        long o = base + (long)(r0 + r) * tstride + tx * 8;
        ull v0 = fadd2(accD[r][0], bA.x);
        ull v1 = fadd2(accD[r][1], bA.y);
        ull v2 = fadd2(accD[r][2], bB.x);
        ull v3 = fadd2(accD[r][3], bB.y);
        if (PASS == 1) {
            ulonglong2 p01 = *reinterpret_cast<const ulonglong2*>(&out[o]);
            ulonglong2 p23 = *reinterpret_cast<const ulonglong2*>(&out[o + 4]);
            v0 = fadd2(v0, p01.x); v1 = fadd2(v1, p01.y);
            v2 = fadd2(v2, p23.x); v3 = fadd2(v3, p23.y);
        }
        ulonglong2 s01; s01.x = v0; s01.y = v1;
        ulonglong2 s23; s23.x = v2; s23.y = v3;
        *reinterpret_cast<ulonglong2*>(&out[o])     = s01;
        *reinterpret_cast<ulonglong2*>(&out[o + 4]) = s23;
    }
}

extern "C" void kernel_launch(void* const* d_in, const int* in_sizes, int n_in,
                              void* d_out, int out_size)
{
    const float* x    = (const float*)d_in[0];
    const float* Wq0  = (const float*)d_in[1];
    const float* Wkv0 = (const float*)d_in[2];
    const float* Wo0  = (const float*)d_in[3];
    const float* bo0  = (const float*)d_in[4];
    const float* Wq1  = (const float*)d_in[5];
    const float* Wkv1 = (const float*)d_in[6];
    const float* Wo1  = (const float*)d_in[7];
    const float* bo1  = (const float*)d_in[8];
    float* out = (float*)d_out;

    const int smem_floats = 128 * XT_STRIDE      // Xt
                          + 128 * PS_STRIDE      // Ps
                          + 2 * 128 * QO_STRIDE  // Qh, Oh
                          + 5 * 16 * KT_STRIDE;  // KhT, VhT, WqT, WkT, WvT
    const int smem_bytes = smem_floats * 4;      // ~194.8 KB

    cudaFuncSetAttribute(axial_attn_kernel<0>,
                         cudaFuncAttributeMaxDynamicSharedMemorySize, smem_bytes);
    cudaFuncSetAttribute(axial_attn_kernel<1>,
                         cudaFuncAttributeMaxDynamicSharedMemorySize, smem_bytes);

    axial_attn_kernel<0><<<1024, 256, smem_bytes>>>(x, Wq0, Wkv0, Wo0, bo0, out);
    axial_attn_kernel<1><<<1024, 256, smem_bytes>>>(x, Wq1, Wkv1, Wo1, bo1, out);
}

// round 9
// speedup vs baseline: 2.3902x; 2.1840x over previous
#include <cuda_runtime.h>
#include <cuda_bf16.h>

// AxialAttention via mma.sync.m16n8k16 bf16 with 2-term bf16 split (3 MMAs per tile).
// x[8,128,128,128] fp32, two axial passes, HEADS=8, e=16.
// One CTA per (pass, sequence); 256 threads = 8 warps; warp w owns token rows 16w..16w+16.

typedef unsigned int uint32;

#define NHEADS 8

// split-weight scratch (written by setup kernel each launch)
__device__ __align__(16) __nv_bfloat16 g_WqkvHi[2][NHEADS][48][128]; // [pass][h][n(q16,k16,v16)][k=d]
__device__ __align__(16) __nv_bfloat16 g_WqkvLo[2][NHEADS][48][128];
__device__ __align__(16) __nv_bfloat16 g_WoHi[2][NHEADS][128][16];   // [pass][h][n][k=e]
__device__ __align__(16) __nv_bfloat16 g_WoLo[2][NHEADS][128][16];

__device__ __forceinline__ float trunc_bf16(float x) {
    return __uint_as_float(__float_as_uint(x) & 0xffff0000u);
}
// pack (e0 -> low half, e1 -> high half); h = hi parts, l = residuals
__device__ __forceinline__ void split_pack(float e0, float e1, uint32& h, uint32& l) {
    float h0 = trunc_bf16(e0), h1 = trunc_bf16(e1);
    asm("cvt.rn.bf16x2.f32 %0, %1, %2;" : "=r"(h) : "f"(h1), "f"(h0));
    asm("cvt.rn.bf16x2.f32 %0, %1, %2;" : "=r"(l) : "f"(e1 - h1), "f"(e0 - h0));
}

__device__ __forceinline__ void mma16816(float* c, const uint32* a, const uint32* b) {
    asm volatile("mma.sync.aligned.m16n8k16.row.col.f32.bf16.bf16.f32 "
                 "{%0,%1,%2,%3}, {%4,%5,%6,%7}, {%8,%9}, {%0,%1,%2,%3};"
                 : "+f"(c[0]), "+f"(c[1]), "+f"(c[2]), "+f"(c[3])
                 : "r"(a[0]), "r"(a[1]), "r"(a[2]), "r"(a[3]), "r"(b[0]), "r"(b[1]));
}

// ---------------- setup: split weights into bf16 hi/lo scratch ----------------
__global__ void split_weights_kernel(const float* __restrict__ Wq0, const float* __restrict__ Wkv0,
                                     const float* __restrict__ Wo0,
                                     const float* __restrict__ Wq1, const float* __restrict__ Wkv1,
                                     const float* __restrict__ Wo1)
{
    int idx = blockIdx.x * blockDim.x + threadIdx.x;
    if (idx < 2 * NHEADS * 48 * 128) {
        int k = idx & 127;
        int n = (idx >> 7) % 48;
        int h = ((idx >> 7) / 48) % NHEADS;
        int p = idx / (128 * 48 * NHEADS);
        const float* Wq  = p ? Wq1  : Wq0;
        const float* Wkv = p ? Wkv1 : Wkv0;
        float v;
        if (n < 16)      v = Wq [k * 128 + h * 16 + n];
        else if (n < 32) v = Wkv[k * 256 + h * 16 + (n - 16)];
        else             v = Wkv[k * 256 + 128 + h * 16 + (n - 32)];
        float hi = trunc_bf16(v);
        g_WqkvHi[p][h][n][k] = __float2bfloat16(hi);
        g_WqkvLo[p][h][n][k] = __float2bfloat16(v - hi);
    }
    if (idx < 2 * NHEADS * 128 * 16) {
        int e = idx & 15;
        int n = (idx >> 4) & 127;
        int h = (idx >> 11) & 7;
        int p = idx >> 14;
        const float* Wo = p ? Wo1 : Wo0;
        float v = Wo[(h * 16 + e) * 128 + n];
        float hi = trunc_bf16(v);
        g_WoHi[p][h][n][e] = __float2bfloat16(hi);
        g_WoLo[p][h][n][e] = __float2bfloat16(v - hi);
    }
}

// ---------------- main fused kernel ----------------
// smem layout strides (halves)
#define XS 136   // sX [128 t][136]
#define WS 136   // sWs [48 n][136]
#define KS 24    // sK [128 j][24]
#define VS 136   // sV [16 e][136]
#define OS 24    // sWo [128 n][24]

template <int PASS>
__launch_bounds__(256)
__global__ void axial_mma_kernel(const float* __restrict__ x,
                                 const float* __restrict__ bo,
                                 float* __restrict__ out)
{
    extern __shared__ __nv_bfloat16 sm[];
    __nv_bfloat16* sXhi  = sm;
    __nv_bfloat16* sXlo  = sXhi  + 128 * XS;
    __nv_bfloat16* sWsHi = sXlo  + 128 * XS;
    __nv_bfloat16* sWsLo = sWsHi + 48 * WS;
    __nv_bfloat16* sKhi  = sWsLo + 48 * WS;
    __nv_bfloat16* sKlo  = sKhi  + 128 * KS;
    __nv_bfloat16* sVhi  = sKlo  + 128 * KS;
    __nv_bfloat16* sVlo  = sVhi  + 16 * VS;
    __nv_bfloat16* sWoHi = sVlo  + 16 * VS;
    __nv_bfloat16* sWoLo = sWoHi + 128 * OS;

    const int tid = threadIdx.x;
    const int w   = tid >> 5;        // warp 0..7
    const int ln  = tid & 31;
    const int g   = ln >> 2;         // group row 0..7
    const int t4  = ln & 3;
    const int s   = blockIdx.x;

    long base;
    int  tstride;
    if (PASS == 0) { base = (long)(s >> 7) * 2097152 + (long)(s & 127) * 128; tstride = 16384; }
    else           { base = (long)s * 16384;                                  tstride = 128;   }

    // ---- load X, split to bf16 hi/lo in smem [t][d] ----
    for (int i = tid; i < 128 * 32; i += 256) {
        int t = i >> 5, c = (i & 31) << 2;
        float4 v = *reinterpret_cast<const float4*>(x + base + (long)t * tstride + c);
        uint32 h0, l0, h1, l1;
        split_pack(v.x, v.y, h0, l0);
        split_pack(v.z, v.w, h1, l1);
        *reinterpret_cast<uint32*>(&sXhi[t * XS + c])     = h0;
        *reinterpret_cast<uint32*>(&sXhi[t * XS + c + 2]) = h1;
        *reinterpret_cast<uint32*>(&sXlo[t * XS + c])     = l0;
        *reinterpret_cast<uint32*>(&sXlo[t * XS + c + 2]) = l1;
    }

    float accD[16][4];
#pragma unroll
    for (int i = 0; i < 16; ++i)
#pragma unroll
        for (int j = 0; j < 4; ++j) accD[i][j] = 0.0f;

#pragma unroll 1
    for (int h = 0; h < NHEADS; ++h) {
        __syncthreads();   // prior head done reading staged buffers / first: X ready

        // ---- stage per-head weights into smem ----
        for (int j = tid; j < 48 * 16; j += 256) {
            int n = j >> 4, ko = (j & 15) << 3;
            *reinterpret_cast<uint4*>(&sWsHi[n * WS + ko]) =
                *reinterpret_cast<const uint4*>(&g_WqkvHi[PASS][h][n][ko]);
            *reinterpret_cast<uint4*>(&sWsLo[n * WS + ko]) =
                *reinterpret_cast<const uint4*>(&g_WqkvLo[PASS][h][n][ko]);
        }
        for (int j = tid; j < 128 * 2; j += 256) {
            int n = j >> 1, ko = (j & 1) << 3;
            *reinterpret_cast<uint4*>(&sWoHi[n * OS + ko]) =
                *reinterpret_cast<const uint4*>(&g_WoHi[PASS][h][n][ko]);
            *reinterpret_cast<uint4*>(&sWoLo[n * OS + ko]) =
                *reinterpret_cast<const uint4*>(&g_WoLo[PASS][h][n][ko]);
        }
        __syncthreads();

        // ---- A: QKV = X @ Wqkv_head  (rows 16w..+16, 48 cols = 6 n-tiles) ----
        float qkv[6][4];
#pragma unroll
        for (int i = 0; i < 6; ++i)
#pragma unroll
            for (int j = 0; j < 4; ++j) qkv[i][j] = 0.0f;

#pragma unroll 1
        for (int kt = 0; kt < 8; ++kt) {
            uint32 ah[4], al[4];
            int xb = (16 * w + g) * XS + kt * 16 + t4 * 2;
            ah[0] = *reinterpret_cast<uint32*>(&sXhi[xb]);
            ah[1] = *reinterpret_cast<uint32*>(&sXhi[xb + 8 * XS]);
            ah[2] = *reinterpret_cast<uint32*>(&sXhi[xb + 8]);
            ah[3] = *reinterpret_cast<uint32*>(&sXhi[xb + 8 * XS + 8]);
            al[0] = *reinterpret_cast<uint32*>(&sXlo[xb]);
            al[1] = *reinterpret_cast<uint32*>(&sXlo[xb + 8 * XS]);
            al[2] = *reinterpret_cast<uint32*>(&sXlo[xb + 8]);
            al[3] = *reinterpret_cast<uint32*>(&sXlo[xb + 8 * XS + 8]);
#pragma unroll
            for (int nt = 0; nt < 6; ++nt) {
                int wb = (8 * nt + g) * WS + kt * 16 + t4 * 2;
                uint32 bh[2], bl[2];
                bh[0] = *reinterpret_cast<uint32*>(&sWsHi[wb]);
                bh[1] = *reinterpret_cast<uint32*>(&sWsHi[wb + 8]);
                bl[0] = *reinterpret_cast<uint32*>(&sWsLo[wb]);
                bl[1] = *reinterpret_cast<uint32*>(&sWsLo[wb + 8]);
                mma16816(qkv[nt], ah, bh);
                mma16816(qkv[nt], ah, bl);
                mma16816(qkv[nt], al, bh);
            }
        }

        // ---- Q: C-frags -> A-frags directly (no smem) ----
        uint32 qh[4], ql[4];
        split_pack(qkv[0][0], qkv[0][1], qh[0], ql[0]);
        split_pack(qkv[0][2], qkv[0][3], qh[1], ql[1]);
        split_pack(qkv[1][0], qkv[1][1], qh[2], ql[2]);
        split_pack(qkv[1][2], qkv[1][3], qh[3], ql[3]);

        // ---- K -> sK[j][e] (B operand for S), packed pair stores ----
#pragma unroll
        for (int tk = 0; tk < 2; ++tk) {
            uint32 h0, l0, h1, l1;
            split_pack(qkv[2 + tk][0], qkv[2 + tk][1], h0, l0);
            split_pack(qkv[2 + tk][2], qkv[2 + tk][3], h1, l1);
            int kb = (16 * w + g) * KS + tk * 8 + t4 * 2;
            *reinterpret_cast<uint32*>(&sKhi[kb])          = h0;
            *reinterpret_cast<uint32*>(&sKhi[kb + 8 * KS]) = h1;
            *reinterpret_cast<uint32*>(&sKlo[kb])          = l0;
            *reinterpret_cast<uint32*>(&sKlo[kb + 8 * KS]) = l1;
        }
        // ---- V -> sV[e][j] (B operand for O), scalar stores ----
#pragma unroll
        for (int tv = 0; tv < 2; ++tv) {
            int e0 = tv * 8 + t4 * 2;
            int j0 = 16 * w + g;
            float c0 = qkv[4 + tv][0], c1 = qkv[4 + tv][1];
            float c2 = qkv[4 + tv][2], c3 = qkv[4 + tv][3];
            float hv;
            hv = trunc_bf16(c0); sVhi[e0 * VS + j0] = __float2bfloat16(hv);
            sVlo[e0 * VS + j0] = __float2bfloat16(c0 - hv);
            hv = trunc_bf16(c1); sVhi[(e0 + 1) * VS + j0] = __float2bfloat16(hv);
            sVlo[(e0 + 1) * VS + j0] = __float2bfloat16(c1 - hv);
            hv = trunc_bf16(c2); sVhi[e0 * VS + j0 + 8] = __float2bfloat16(hv);
            sVlo[e0 * VS + j0 + 8] = __float2bfloat16(c2 - hv);
            hv = trunc_bf16(c3); sVhi[(e0 + 1) * VS + j0 + 8] = __float2bfloat16(hv);
            sVlo[(e0 + 1) * VS + j0 + 8] = __float2bfloat16(c3 - hv);
        }
        __syncthreads();

        // ---- B: S = Q @ K^T  (16 n-tiles over j, K-dim = 16) ----
        float S[16][4];
#pragma unroll
        for (int nt = 0; nt < 16; ++nt) {
#pragma unroll
            for (int j = 0; j < 4; ++j) S[nt][j] = 0.0f;
            int kb = (8 * nt + g) * KS + t4 * 2;
            uint32 bh[2], bl[2];
            bh[0] = *reinterpret_cast<uint32*>(&sKhi[kb]);
            bh[1] = *reinterpret_cast<uint32*>(&sKhi[kb + 8]);
            bl[0] = *reinterpret_cast<uint32*>(&sKlo[kb]);
            bl[1] = *reinterpret_cast<uint32*>(&sKlo[kb + 8]);
            mma16816(S[nt], qh, bh);
            mma16816(S[nt], qh, bl);
            mma16816(S[nt], ql, bh);
        }

        // ---- softmax over j (rows g and g+8 of this warp's 16) ----
        float mA = -1e30f, mB = -1e30f;
#pragma unroll
        for (int nt = 0; nt < 16; ++nt) {
            S[nt][0] *= 0.25f; S[nt][1] *= 0.25f; S[nt][2] *= 0.25f; S[nt][3] *= 0.25f;
            mA = fmaxf(mA, fmaxf(S[nt][0], S[nt][1]));
            mB = fmaxf(mB, fmaxf(S[nt][2], S[nt][3]));
        }
        mA = fmaxf(mA, __shfl_xor_sync(0xffffffffu, mA, 1));
        mA = fmaxf(mA, __shfl_xor_sync(0xffffffffu, mA, 2));
        mB = fmaxf(mB, __shfl_xor_sync(0xffffffffu, mB, 1));
        mB = fmaxf(mB, __shfl_xor_sync(0xffffffffu, mB, 2));
        float sA = 0.0f, sB = 0.0f;
#pragma unroll
        for (int nt = 0; nt < 16; ++nt) {
            S[nt][0] = __expf(S[nt][0] - mA); sA += S[nt][0];
            S[nt][1] = __expf(S[nt][1] - mA); sA += S[nt][1];
            S[nt][2] = __expf(S[nt][2] - mB); sB += S[nt][2];
            S[nt][3] = __expf(S[nt][3] - mB); sB += S[nt][3];
        }
        sA += __shfl_xor_sync(0xffffffffu, sA, 1);
        sA += __shfl_xor_sync(0xffffffffu, sA, 2);
        sB += __shfl_xor_sync(0xffffffffu, sB, 1);
        sB += __shfl_xor_sync(0xffffffffu, sB, 2);
        float iA = 1.0f / sA, iB = 1.0f / sB;
#pragma unroll
        for (int nt = 0; nt < 16; ++nt) {
            S[nt][0] *= iA; S[nt][1] *= iA; S[nt][2] *= iB; S[nt][3] *= iB;
        }

        // ---- C: O = P @ V  (P from S regs -> A-frags, V from sV[e][j]) ----
        float o[2][4];
#pragma unroll
        for (int i = 0; i < 2; ++i)
#pragma unroll
            for (int j = 0; j < 4; ++j) o[i][j] = 0.0f;
#pragma unroll
        for (int kt = 0; kt < 8; ++kt) {
            uint32 ph[4], pl[4];
            split_pack(S[2 * kt][0],     S[2 * kt][1],     ph[0], pl[0]);
            split_pack(S[2 * kt][2],     S[2 * kt][3],     ph[1], pl[1]);
            split_pack(S[2 * kt + 1][0], S[2 * kt + 1][1], ph[2], pl[2]);
            split_pack(S[2 * kt + 1][2], S[2 * kt + 1][3], ph[3], pl[3]);
#pragma unroll
            for (int nt = 0; nt < 2; ++nt) {
                int vb = (8 * nt + g) * VS + kt * 16 + t4 * 2;
                uint32 bh[2], bl[2];
                bh[0] = *reinterpret_cast<uint32*>(&sVhi[vb]);
                bh[1] = *reinterpret_cast<uint32*>(&sVhi[vb + 8]);
                bl[0] = *reinterpret_cast<uint32*>(&sVlo[vb]);
                bl[1] = *reinterpret_cast<uint32*>(&sVlo[vb + 8]);
                mma16816(o[nt], ph, bh);
                mma16816(o[nt], ph, bl);
                mma16816(o[nt], pl, bh);
            }
        }

        // ---- D: accD += O @ Wo_head  (O frags direct, K-dim = 16) ----
        uint32 oh[4], ol[4];
        split_pack(o[0][0], o[0][1], oh[0], ol[0]);
        split_pack(o[0][2], o[0][3], oh[1], ol[1]);
        split_pack(o[1][0], o[1][1], oh[2], ol[2]);
        split_pack(o[1][2], o[1][3], oh[3], ol[3]);
#pragma unroll
        for (int nt = 0; nt < 16; ++nt) {
            int wb = (8 * nt + g) * OS + t4 * 2;
            uint32 bh[2], bl[2];
            bh[0] = *reinterpret_cast<uint32*>(&sWoHi[wb]);
            bh[1] = *reinterpret_cast<uint32*>(&sWoHi[wb + 8]);
            bl[0] = *reinterpret_cast<uint32*>(&sWoLo[wb]);
            bl[1] = *reinterpret_cast<uint32*>(&sWoLo[wb + 8]);
            mma16816(accD[nt], oh, bh);
            mma16816(accD[nt], oh, bl);
            mma16816(accD[nt], ol, bh);
        }
    }

    // ---- epilogue: + bias; write (pass 0) or RMW (pass 1) ----
    int row0 = 16 * w + g;
#pragma unroll
    for (int nt = 0; nt < 16; ++nt) {
        int col = 8 * nt + t4 * 2;
        float2 b = *reinterpret_cast<const float2*>(&bo[col]);
        long o0 = base + (long)row0 * tstride + col;
        long o1 = base + (long)(row0 + 8) * tstride + col;
        float2 v0, v1;
        v0.x = accD[nt][0] + b.x; v0.y = accD[nt][1] + b.y;
        v1.x = accD[nt][2] + b.x; v1.y = accD[nt][3] + b.y;
        if (PASS == 1) {
            float2 p0 = *reinterpret_cast<const float2*>(&out[o0]);
            float2 p1 = *reinterpret_cast<const float2*>(&out[o1]);
            v0.x += p0.x; v0.y += p0.y;
            v1.x += p1.x; v1.y += p1.y;
        }
        *reinterpret_cast<float2*>(&out[o0]) = v0;
        *reinterpret_cast<float2*>(&out[o1]) = v1;
    }
}

extern "C" void kernel_launch(void* const* d_in, const int* in_sizes, int n_in,
                              void* d_out, int out_size)
{
    const float* x    = (const float*)d_in[0];
    const float* Wq0  = (const float*)d_in[1];
    const float* Wkv0 = (const float*)d_in[2];
    const float* Wo0  = (const float*)d_in[3];
    const float* bo0  = (const float*)d_in[4];
    const float* Wq1  = (const float*)d_in[5];
    const float* Wkv1 = (const float*)d_in[6];
    const float* Wo1  = (const float*)d_in[7];
    const float* bo1  = (const float*)d_in[8];
    float* out = (float*)d_out;

    const int smem_halves = 2 * 128 * XS + 2 * 48 * WS + 2 * 128 * KS
                          + 2 * 16 * VS + 2 * 128 * OS;
    const int smem_bytes = smem_halves * 2;   // 129,024 B

    cudaFuncSetAttribute(axial_mma_kernel<0>,
                         cudaFuncAttributeMaxDynamicSharedMemorySize, smem_bytes);
    cudaFuncSetAttribute(axial_mma_kernel<1>,
                         cudaFuncAttributeMaxDynamicSharedMemorySize, smem_bytes);

    split_weights_kernel<<<384, 256>>>(Wq0, Wkv0, Wo0, Wq1, Wkv1, Wo1);
    axial_mma_kernel<0><<<1024, 256, smem_bytes>>>(x, bo0, out);
    axial_mma_kernel<1><<<1024, 256, smem_bytes>>>(x, bo1, out);
}